// round 11
// baseline (speedup 1.0000x reference)
#include <cuda_runtime.h>
#include <cuda_fp16.h>
#include <cstdint>

#define K_DIM 1024
#define N_DIM 4096
#define M_DIM 4096

// Scratch (allocation-free).
__device__ __half g_Wh[(size_t)N_DIM * K_DIM];      // TRANSPOSED: [n][k], fp16
__device__ __half g_Xh[(size_t)M_DIM * K_DIM];      // X, fp16

__device__ __forceinline__ uint32_t smem_u32(const void* p) {
    uint32_t a;
    asm("{ .reg .u64 t; cvta.to.shared.u64 t, %1; cvt.u32.u64 %0, t; }" : "=r"(a) : "l"(p));
    return a;
}

// ---------------- Merged prep: X->fp16 convert AND W-from-cores, one launch ----------------
// Blocks [0,2048): x_half. Blocks [2048,2560): stageW (b = blk-2048 = (n1,n2,n3)).
__global__ __launch_bounds__(256) void tt_prep(const float* __restrict__ X,
                                               const float* __restrict__ core0,
                                               const float* __restrict__ core1,
                                               const float* __restrict__ core2,
                                               const float* __restrict__ core3) {
    const int tid = threadIdx.x;
    if (blockIdx.x < 2048) {
        int i = blockIdx.x * 256 + tid;              // 524288
        float4 v0 = ((const float4*)X)[2 * i];
        float4 v1 = ((const float4*)X)[2 * i + 1];
        __half2 h[4];
        h[0] = __floats2half2_rn(v0.x, v0.y);
        h[1] = __floats2half2_rn(v0.z, v0.w);
        h[2] = __floats2half2_rn(v1.x, v1.y);
        h[3] = __floats2half2_rn(v1.z, v1.w);
        ((uint4*)g_Xh)[i] = *(uint4*)h;
        return;
    }

    __shared__ float sC0[128];    // [m1][r1]           (n1 fixed)
    __shared__ float sC1[2048];   // [r1][m2][r2]       (n2 fixed)
    __shared__ float sC2[1024];   // [r2][m3][r3]       (n3 fixed)
    __shared__ float sC3[512];    // [r3][m4][n4]

    const int b = blockIdx.x - 2048;                  // 512 = (n1,n2,n3)
    const int n1 = b >> 6, n2 = (b >> 3) & 7, n3 = b & 7;

    if (tid < 32) {
        int m1 = tid >> 2, r1q = tid & 3;
        ((float4*)sC0)[tid] = *(const float4*)&core0[(m1 * 8 + n1) * 16 + r1q * 4];
    }
#pragma unroll
    for (int rd = 0; rd < 2; rd++) {
        int c = rd * 256 + tid;
        int r1 = c >> 5, m2 = (c >> 2) & 7, r2q = c & 3;
        ((float4*)sC1)[c] = *(const float4*)&core1[r1 * 1024 + m2 * 128 + n2 * 16 + r2q * 4];
    }
    {
        int r2 = tid >> 4, m3 = (tid >> 2) & 3, r3q = tid & 3;
        ((float4*)sC2)[tid] = *(const float4*)&core2[r2 * 512 + m3 * 128 + n3 * 16 + r3q * 4];
    }
    if (tid < 128) ((float4*)sC3)[tid] = ((const float4*)core3)[tid];
    __syncthreads();

    const int m1 = tid >> 5, m2 = (tid >> 2) & 7, m3 = tid & 3;
    float a[16], t[16];
#pragma unroll
    for (int r2 = 0; r2 < 16; r2++) a[r2] = 0.f;
#pragma unroll
    for (int r1 = 0; r1 < 16; r1++) {
        float c0v = sC0[m1 * 16 + r1];
#pragma unroll
        for (int r2 = 0; r2 < 16; r2++) a[r2] += c0v * sC1[r1 * 128 + m2 * 16 + r2];
    }
#pragma unroll
    for (int r3 = 0; r3 < 16; r3++) t[r3] = 0.f;
#pragma unroll
    for (int r2 = 0; r2 < 16; r2++) {
        float av = a[r2];
#pragma unroll
        for (int r3 = 0; r3 < 16; r3++) t[r3] += av * sC2[r2 * 64 + m3 * 16 + r3];
    }

    const size_t nbase = (size_t)b * 8;
#pragma unroll
    for (int n4 = 0; n4 < 8; n4++) {
        float s[4];
#pragma unroll
        for (int m4 = 0; m4 < 4; m4++) {
            float acc = 0.f;
#pragma unroll
            for (int r3 = 0; r3 < 16; r3++) acc += t[r3] * sC3[r3 * 32 + m4 * 8 + n4];
            s[m4] = acc;
        }
        __half* dst = &g_Wh[(nbase + n4) * K_DIM + tid * 4];
        *(__half2*)dst       = __floats2half2_rn(s[0], s[1]);
        *(__half2*)(dst + 2) = __floats2half2_rn(s[2], s[3]);
    }
}

// ---------------- fp16 mma.sync GEMM: ldmatrix + BK=64, 3-stage cp.async ----------------
// CTA 128x128, 256 threads (8 warps 2x4), warp tile 64x32 -> 4 warps/SMSP at 2 CTAs/SM.
// Smem rows 128B = 8x16B units, SW128 swizzle: unit ^= row&7.

#define BK 64
#define A_BYTES 16384                // 128 rows x 128B
#define STAGE_BYTES 32768            // A 16KB + B 16KB
#define NSTAGE 3
#define SMEM_SZ (NSTAGE * STAGE_BYTES)
#define NITER (K_DIM / BK)

__device__ __forceinline__ void cp16(uint32_t dst, const void* src) {
    asm volatile("cp.async.cg.shared.global [%0], [%1], 16;" :: "r"(dst), "l"(src) : "memory");
}
#define LDSM4(r0, r1, r2, r3, addr)                                          \
    asm volatile("ldmatrix.sync.aligned.m8n8.x4.shared.b16 {%0,%1,%2,%3},[%4];" \
        : "=r"(r0), "=r"(r1), "=r"(r2), "=r"(r3) : "r"(addr))

__global__ __launch_bounds__(256, 2) void tt_gemm5(const float* __restrict__ bias,
                                                   float* __restrict__ Y) {
    extern __shared__ __align__(1024) char smem[];
    const uint32_t sb = smem_u32(smem);
    const int tid = threadIdx.x, lane = tid & 31, warp = tid >> 5;
    const int wm = warp >> 2, wn = warp & 3;          // 2 x 4 warp grid, tile 64x32
    const int g = lane >> 2, t = lane & 3;
    const int bm = blockIdx.y * 128, bn = blockIdx.x * 128;

    const __half* gA = g_Xh + (size_t)bm * K_DIM;
    const __half* gB = g_Wh + (size_t)bn * K_DIM;

    float acc[4][4][4];
#pragma unroll
    for (int a = 0; a < 4; a++)
#pragma unroll
        for (int b = 0; b < 4; b++)
#pragma unroll
            for (int c = 0; c < 4; c++) acc[a][b][c] = 0.f;

    // cp.async: chunk c = i*256 + tid -> row m = c>>3, unit j = c&7 (1024 chunks/operand).
    auto issue = [&](int it) {
        if (it < NITER) {
            const int s = it % NSTAGE;
            const uint32_t a0 = sb + s * STAGE_BYTES;
            const uint32_t b0 = a0 + A_BYTES;
            const int kt = it * BK;
#pragma unroll
            for (int i = 0; i < 4; i++) {
                int c = i * 256 + tid;
                int m = c >> 3, j = c & 7;
                uint32_t off = (uint32_t)(m * 128 + ((j ^ (m & 7)) << 4));
                cp16(a0 + off, gA + (size_t)m * K_DIM + kt + j * 8);
                cp16(b0 + off, gB + (size_t)m * K_DIM + kt + j * 8);
            }
        }
        asm volatile("cp.async.commit_group;" ::: "memory");
    };

    issue(0); issue(1);

    // ldmatrix lane geometry (row offsets multiples of 8 -> r7 = lane&7 everywhere).
    const int r7  = lane & 7;
    const int uAp = lane >> 4;          // A: lanes 16-31 take the hi 16B unit
    const int uBp = (lane >> 3) & 1;    // B: phase pairs alternate units
    uint32_t baseA[4], baseB[2];
#pragma unroll
    for (int mt = 0; mt < 4; mt++)
        baseA[mt] = (uint32_t)((wm * 64 + mt * 16 + (lane & 15)) * 128);
#pragma unroll
    for (int p = 0; p < 2; p++)
        baseB[p] = (uint32_t)((wn * 32 + p * 16 + ((lane >> 4) << 3) + (lane & 7)) * 128);

    for (int it = 0; it < NITER; it++) {
        const int s = it % NSTAGE;
        asm volatile("cp.async.wait_group 1;" ::: "memory");
        __syncthreads();
        issue(it + 2);                   // stage (it+2)%3: last read at iter it-1
        const uint32_t a0 = sb + s * STAGE_BYTES;
        const uint32_t b0 = a0 + A_BYTES;

#pragma unroll
        for (int kk = 0; kk < 4; kk++) { // K sub-step of 16
            const uint32_t oA = (uint32_t)(((2 * kk + uAp) ^ r7) << 4);
            const uint32_t oB = (uint32_t)(((2 * kk + uBp) ^ r7) << 4);
            unsigned a[4][4], b[4][2];
#pragma unroll
            for (int mt = 0; mt < 4; mt++)
                LDSM4(a[mt][0], a[mt][1], a[mt][2], a[mt][3], a0 + baseA[mt] + oA);
#pragma unroll
            for (int p = 0; p < 2; p++)
                LDSM4(b[2 * p][0], b[2 * p][1], b[2 * p + 1][0], b[2 * p + 1][1],
                      b0 + baseB[p] + oB);
#pragma unroll
            for (int mt = 0; mt < 4; mt++)
#pragma unroll
                for (int nt = 0; nt < 4; nt++) {
                    asm volatile(
                        "mma.sync.aligned.m16n8k16.row.col.f32.f16.f16.f32 "
                        "{%0,%1,%2,%3},{%4,%5,%6,%7},{%8,%9},{%0,%1,%2,%3};"
                        : "+f"(acc[mt][nt][0]), "+f"(acc[mt][nt][1]),
                          "+f"(acc[mt][nt][2]), "+f"(acc[mt][nt][3])
                        : "r"(a[mt][0]), "r"(a[mt][1]), "r"(a[mt][2]), "r"(a[mt][3]),
                          "r"(b[nt][0]), "r"(b[nt][1]));
                }
        }
    }

    // Epilogue: bias add + float2 stores.
#pragma unroll
    for (int mt = 0; mt < 4; mt++) {
        size_t r0 = (size_t)(bm + wm * 64 + mt * 16 + g);
#pragma unroll
        for (int nt = 0; nt < 4; nt++) {
            int col = bn + wn * 32 + nt * 8 + 2 * t;
            float b0v = bias[col], b1v = bias[col + 1];
            *(float2*)&Y[r0 * N_DIM + col] =
                make_float2(acc[mt][nt][0] + b0v, acc[mt][nt][1] + b1v);
            *(float2*)&Y[(r0 + 8) * N_DIM + col] =
                make_float2(acc[mt][nt][2] + b0v, acc[mt][nt][3] + b1v);
        }
    }
}

extern "C" void kernel_launch(void* const* d_in, const int* in_sizes, int n_in,
                              void* d_out, int out_size) {
    const float* x     = (const float*)d_in[0];
    const float* core0 = (const float*)d_in[1];
    const float* core1 = (const float*)d_in[2];
    const float* core2 = (const float*)d_in[3];
    const float* core3 = (const float*)d_in[4];
    const float* bias  = (const float*)d_in[5];
    float* y = (float*)d_out;

    cudaFuncSetAttribute(tt_gemm5, cudaFuncAttributeMaxDynamicSharedMemorySize, SMEM_SZ);

    tt_prep<<<2560, 256>>>(x, core0, core1, core2, core3);

    dim3 grid(N_DIM / 128, M_DIM / 128);   // 32 x 32
    tt_gemm5<<<grid, 256, SMEM_SZ>>>(bias, y);
}

// round 13
// speedup vs baseline: 1.0592x; 1.0592x over previous
#include <cuda_runtime.h>
#include <cuda_fp16.h>
#include <cstdint>

#define K_DIM 1024
#define N_DIM 4096
#define M_DIM 4096

// Scratch (allocation-free).
__device__ __half g_Wh[(size_t)N_DIM * K_DIM];      // TRANSPOSED: [n][k], fp16
__device__ __half g_Xh[(size_t)M_DIM * K_DIM];      // X, fp16

__device__ __forceinline__ uint32_t smem_u32(const void* p) {
    uint32_t a;
    asm("{ .reg .u64 t; cvta.to.shared.u64 t, %1; cvt.u32.u64 %0, t; }" : "=r"(a) : "l"(p));
    return a;
}

// ---------------- TT-core staging: W from 4 cores (one kernel) ----------------
__global__ __launch_bounds__(256) void tt_stageW(const float* __restrict__ core0,
                                                 const float* __restrict__ core1,
                                                 const float* __restrict__ core2,
                                                 const float* __restrict__ core3) {
    __shared__ float sC0[128];    // [m1][r1]           (n1 fixed)
    __shared__ float sC1[2048];   // [r1][m2][r2]       (n2 fixed)
    __shared__ float sC2[1024];   // [r2][m3][r3]       (n3 fixed)
    __shared__ float sC3[512];    // [r3][m4][n4]

    const int b = blockIdx.x;                         // 512 = (n1,n2,n3)
    const int n1 = b >> 6, n2 = (b >> 3) & 7, n3 = b & 7;
    const int tid = threadIdx.x;

    if (tid < 32) {
        int m1 = tid >> 2, r1q = tid & 3;
        ((float4*)sC0)[tid] = *(const float4*)&core0[(m1 * 8 + n1) * 16 + r1q * 4];
    }
#pragma unroll
    for (int rd = 0; rd < 2; rd++) {
        int c = rd * 256 + tid;
        int r1 = c >> 5, m2 = (c >> 2) & 7, r2q = c & 3;
        ((float4*)sC1)[c] = *(const float4*)&core1[r1 * 1024 + m2 * 128 + n2 * 16 + r2q * 4];
    }
    {
        int r2 = tid >> 4, m3 = (tid >> 2) & 3, r3q = tid & 3;
        ((float4*)sC2)[tid] = *(const float4*)&core2[r2 * 512 + m3 * 128 + n3 * 16 + r3q * 4];
    }
    if (tid < 128) ((float4*)sC3)[tid] = ((const float4*)core3)[tid];
    __syncthreads();

    const int m1 = tid >> 5, m2 = (tid >> 2) & 7, m3 = tid & 3;
    float a[16], t[16];
#pragma unroll
    for (int r2 = 0; r2 < 16; r2++) a[r2] = 0.f;
#pragma unroll
    for (int r1 = 0; r1 < 16; r1++) {
        float c0v = sC0[m1 * 16 + r1];
#pragma unroll
        for (int r2 = 0; r2 < 16; r2++) a[r2] += c0v * sC1[r1 * 128 + m2 * 16 + r2];
    }
#pragma unroll
    for (int r3 = 0; r3 < 16; r3++) t[r3] = 0.f;
#pragma unroll
    for (int r2 = 0; r2 < 16; r2++) {
        float av = a[r2];
#pragma unroll
        for (int r3 = 0; r3 < 16; r3++) t[r3] += av * sC2[r2 * 64 + m3 * 16 + r3];
    }

    const size_t nbase = (size_t)b * 8;
#pragma unroll
    for (int n4 = 0; n4 < 8; n4++) {
        float s[4];
#pragma unroll
        for (int m4 = 0; m4 < 4; m4++) {
            float acc = 0.f;
#pragma unroll
            for (int r3 = 0; r3 < 16; r3++) acc += t[r3] * sC3[r3 * 32 + m4 * 8 + n4];
            s[m4] = acc;
        }
        __half* dst = &g_Wh[(nbase + n4) * K_DIM + tid * 4];
        *(__half2*)dst       = __floats2half2_rn(s[0], s[1]);
        *(__half2*)(dst + 2) = __floats2half2_rn(s[2], s[3]);
    }
}

// Convert X to fp16.
__global__ void x_half(const float* __restrict__ X) {
    int i = blockIdx.x * 256 + threadIdx.x;          // 524288
    float4 v0 = ((const float4*)X)[2 * i];
    float4 v1 = ((const float4*)X)[2 * i + 1];
    __half2 h[4];
    h[0] = __floats2half2_rn(v0.x, v0.y);
    h[1] = __floats2half2_rn(v0.z, v0.w);
    h[2] = __floats2half2_rn(v1.x, v1.y);
    h[3] = __floats2half2_rn(v1.z, v1.w);
    ((uint4*)g_Xh)[i] = *(uint4*)h;
}

// ---------------- fp16 mma.sync GEMM: ldmatrix + BK=64, 3-stage cp.async ----------------
// CTA 128x128, 256 threads (8 warps 2x4), warp tile 64x32 -> 4 warps/SMSP at 2 CTAs/SM.
// Smem rows 128B = 8x16B units, SW128 swizzle: unit ^= row&7.

#define BK 64
#define A_BYTES 16384                // 128 rows x 128B
#define STAGE_BYTES 32768            // A 16KB + B 16KB
#define NSTAGE 3
#define SMEM_SZ (NSTAGE * STAGE_BYTES)
#define NITER (K_DIM / BK)

__device__ __forceinline__ void cp16(uint32_t dst, const void* src) {
    asm volatile("cp.async.cg.shared.global [%0], [%1], 16;" :: "r"(dst), "l"(src) : "memory");
}
#define LDSM4(r0, r1, r2, r3, addr)                                          \
    asm volatile("ldmatrix.sync.aligned.m8n8.x4.shared.b16 {%0,%1,%2,%3},[%4];" \
        : "=r"(r0), "=r"(r1), "=r"(r2), "=r"(r3) : "r"(addr))

__global__ __launch_bounds__(256, 2) void tt_gemm5(const float* __restrict__ bias,
                                                   float* __restrict__ Y) {
    extern __shared__ __align__(1024) char smem[];
    const uint32_t sb = smem_u32(smem);
    const int tid = threadIdx.x, lane = tid & 31, warp = tid >> 5;
    const int wm = warp >> 2, wn = warp & 3;          // 2 x 4 warp grid, tile 64x32
    const int g = lane >> 2, t = lane & 3;
    const int bm = blockIdx.y * 128, bn = blockIdx.x * 128;

    const __half* gA = g_Xh + (size_t)bm * K_DIM;
    const __half* gB = g_Wh + (size_t)bn * K_DIM;

    float acc[4][4][4];
#pragma unroll
    for (int a = 0; a < 4; a++)
#pragma unroll
        for (int b = 0; b < 4; b++)
#pragma unroll
            for (int c = 0; c < 4; c++) acc[a][b][c] = 0.f;

    // cp.async: chunk c = i*256 + tid -> row m = c>>3, unit j = c&7 (1024 chunks/operand).
    auto issue = [&](int it) {
        if (it < NITER) {
            const int s = it % NSTAGE;
            const uint32_t a0 = sb + s * STAGE_BYTES;
            const uint32_t b0 = a0 + A_BYTES;
            const int kt = it * BK;
#pragma unroll
            for (int i = 0; i < 4; i++) {
                int c = i * 256 + tid;
                int m = c >> 3, j = c & 7;
                uint32_t off = (uint32_t)(m * 128 + ((j ^ (m & 7)) << 4));
                cp16(a0 + off, gA + (size_t)m * K_DIM + kt + j * 8);
                cp16(b0 + off, gB + (size_t)m * K_DIM + kt + j * 8);
            }
        }
        asm volatile("cp.async.commit_group;" ::: "memory");
    };

    issue(0); issue(1);

    // ldmatrix lane geometry (row offsets multiples of 8 -> r7 = lane&7 everywhere).
    const int r7  = lane & 7;
    const int uAp = lane >> 4;          // A: lanes 16-31 take the hi 16B unit
    const int uBp = (lane >> 3) & 1;    // B: phase pairs alternate units
    uint32_t baseA[4], baseB[2];
#pragma unroll
    for (int mt = 0; mt < 4; mt++)
        baseA[mt] = (uint32_t)((wm * 64 + mt * 16 + (lane & 15)) * 128);
#pragma unroll
    for (int p = 0; p < 2; p++)
        baseB[p] = (uint32_t)((wn * 32 + p * 16 + ((lane >> 4) << 3) + (lane & 7)) * 128);

    for (int it = 0; it < NITER; it++) {
        const int s = it % NSTAGE;
        asm volatile("cp.async.wait_group 1;" ::: "memory");
        __syncthreads();
        issue(it + 2);                   // stage (it+2)%3: last read at iter it-1
        const uint32_t a0 = sb + s * STAGE_BYTES;
        const uint32_t b0 = a0 + A_BYTES;

#pragma unroll
        for (int kk = 0; kk < 4; kk++) { // K sub-step of 16
            const uint32_t oA = (uint32_t)(((2 * kk + uAp) ^ r7) << 4);
            const uint32_t oB = (uint32_t)(((2 * kk + uBp) ^ r7) << 4);
            unsigned a[4][4], b[4][2];
#pragma unroll
            for (int mt = 0; mt < 4; mt++)
                LDSM4(a[mt][0], a[mt][1], a[mt][2], a[mt][3], a0 + baseA[mt] + oA);
#pragma unroll
            for (int p = 0; p < 2; p++)
                LDSM4(b[2 * p][0], b[2 * p][1], b[2 * p + 1][0], b[2 * p + 1][1],
                      b0 + baseB[p] + oB);
#pragma unroll
            for (int mt = 0; mt < 4; mt++)
#pragma unroll
                for (int nt = 0; nt < 4; nt++) {
                    asm volatile(
                        "mma.sync.aligned.m16n8k16.row.col.f32.f16.f16.f32 "
                        "{%0,%1,%2,%3},{%4,%5,%6,%7},{%8,%9},{%0,%1,%2,%3};"
                        : "+f"(acc[mt][nt][0]), "+f"(acc[mt][nt][1]),
                          "+f"(acc[mt][nt][2]), "+f"(acc[mt][nt][3])
                        : "r"(a[mt][0]), "r"(a[mt][1]), "r"(a[mt][2]), "r"(a[mt][3]),
                          "r"(b[nt][0]), "r"(b[nt][1]));
                }
        }
    }

    // Epilogue: bias add + float2 stores.
#pragma unroll
    for (int mt = 0; mt < 4; mt++) {
        size_t r0 = (size_t)(bm + wm * 64 + mt * 16 + g);
#pragma unroll
        for (int nt = 0; nt < 4; nt++) {
            int col = bn + wn * 32 + nt * 8 + 2 * t;
            float b0v = bias[col], b1v = bias[col + 1];
            *(float2*)&Y[r0 * N_DIM + col] =
                make_float2(acc[mt][nt][0] + b0v, acc[mt][nt][1] + b1v);
            *(float2*)&Y[(r0 + 8) * N_DIM + col] =
                make_float2(acc[mt][nt][2] + b0v, acc[mt][nt][3] + b1v);
        }
    }
}

extern "C" void kernel_launch(void* const* d_in, const int* in_sizes, int n_in,
                              void* d_out, int out_size) {
    const float* x     = (const float*)d_in[0];
    const float* core0 = (const float*)d_in[1];
    const float* core1 = (const float*)d_in[2];
    const float* core2 = (const float*)d_in[3];
    const float* core3 = (const float*)d_in[4];
    const float* bias  = (const float*)d_in[5];
    float* y = (float*)d_out;

    cudaFuncSetAttribute(tt_gemm5, cudaFuncAttributeMaxDynamicSharedMemorySize, SMEM_SZ);

    x_half<<<2048, 256>>>(x);
    tt_stageW<<<512, 256>>>(core0, core1, core2, core3);

    dim3 grid(N_DIM / 128, M_DIM / 128);   // 32 x 32
    tt_gemm5<<<grid, 256, SMEM_SZ>>>(bias, y);
}